// round 7
// baseline (speedup 1.0000x reference)
#include <cuda_runtime.h>

#define MAX_N 100000
#define D 64

// Scratch (device globals: sanctioned alternative to cudaMalloc)
__device__ float g_h[MAX_N * D];     // h = x @ W^T
__device__ float g_deg[MAX_N];
__device__ float g_dinv[MAX_N];

// ---------------------------------------------------------------------------
// 1) degree init: every node gets a self-loop -> deg starts at 1
// ---------------------------------------------------------------------------
__global__ void deg_init_kernel(int N4) {
    int i = blockIdx.x * blockDim.x + threadIdx.x;
    if (i < N4) ((float4*)g_deg)[i] = make_float4(1.f, 1.f, 1.f, 1.f);
}

// 2) accumulate in-degree over edge dst (edge_index is int32)
__global__ void deg_acc_kernel(const int* __restrict__ ei, int E) {
    int e = blockIdx.x * blockDim.x + threadIdx.x;
    if (e < E) atomicAdd(&g_deg[ei[E + e]], 1.0f);
}

// ---------------------------------------------------------------------------
// 3) GEMM: h[n][o] = sum_k x[n][k] * W[o][k]
//    Warp-uniform tiling: warp = (node-group, output-quarter q). All 32 lanes
//    share q -> W smem loads are pure broadcast LDS.128 (conflict-free), and
//    each load feeds 32 nodes. Lane owns 1 node x 16 outputs (8 f32x2 accs).
//    Epilogue: dinv[n] = rsqrt(deg[n]) (fused),
//              out[n][o] = h[n][o]*dinv[n]^2 + b[o]  (self-loop + bias,
//              fully initializes the poisoned output buffer).
// ---------------------------------------------------------------------------
__global__ __launch_bounds__(256)
void gemm_kernel(const float* __restrict__ x,
                 const float* __restrict__ W,
                 const float* __restrict__ bias,
                 float* __restrict__ out, int N) {
    __shared__ float Ws[D * D];   // Ws[k*64 + o] = W[o][k]  (transposed)
    for (int t = threadIdx.x; t < D * D; t += 256) {
        int o = t >> 6;
        int k = t & 63;
        Ws[k * D + o] = W[t];
    }
    __syncthreads();

    int w    = threadIdx.x >> 5;          // warp 0..7
    int lane = threadIdx.x & 31;
    int q    = w & 3;                     // output quarter (warp-uniform!)
    int n    = blockIdx.x * 64 + (w >> 2) * 32 + lane;
    if (n >= N) return;

    unsigned long long acc[8];
#pragma unroll
    for (int m = 0; m < 8; m++) acc[m] = 0ULL;

    const float4* xr = (const float4*)(x + (size_t)n * D);

#pragma unroll 1
    for (int i4 = 0; i4 < 16; i4++) {
        float4 xv = xr[i4];
        float xs[4] = {xv.x, xv.y, xv.z, xv.w};
#pragma unroll
        for (int kk = 0; kk < 4; kk++) {
            int k = i4 * 4 + kk;
            unsigned long long xx;
            asm("mov.b64 %0, {%1, %1};" : "=l"(xx) : "f"(xs[kk]));
            const ulonglong2* wp = (const ulonglong2*)(Ws + k * D + q * 16);
            ulonglong2 w0 = wp[0], w1 = wp[1], w2 = wp[2], w3 = wp[3];
            asm("fma.rn.f32x2 %0, %1, %2, %0;" : "+l"(acc[0]) : "l"(xx), "l"(w0.x));
            asm("fma.rn.f32x2 %0, %1, %2, %0;" : "+l"(acc[1]) : "l"(xx), "l"(w0.y));
            asm("fma.rn.f32x2 %0, %1, %2, %0;" : "+l"(acc[2]) : "l"(xx), "l"(w1.x));
            asm("fma.rn.f32x2 %0, %1, %2, %0;" : "+l"(acc[3]) : "l"(xx), "l"(w1.y));
            asm("fma.rn.f32x2 %0, %1, %2, %0;" : "+l"(acc[4]) : "l"(xx), "l"(w2.x));
            asm("fma.rn.f32x2 %0, %1, %2, %0;" : "+l"(acc[5]) : "l"(xx), "l"(w2.y));
            asm("fma.rn.f32x2 %0, %1, %2, %0;" : "+l"(acc[6]) : "l"(xx), "l"(w3.x));
            asm("fma.rn.f32x2 %0, %1, %2, %0;" : "+l"(acc[7]) : "l"(xx), "l"(w3.y));
        }
    }

    float dv = rsqrtf(g_deg[n]);
    if (q == 0) g_dinv[n] = dv;
    float sl = dv * dv;

    float* hrow = g_h + (size_t)n * D + q * 16;
    float* orow = out + (size_t)n * D + q * 16;
    const float4* brow = (const float4*)(bias + q * 16);   // warp-uniform
#pragma unroll
    for (int m = 0; m < 4; m++) {
        float f0, f1, f2, f3;
        asm("mov.b64 {%0, %1}, %2;" : "=f"(f0), "=f"(f1) : "l"(acc[2 * m]));
        asm("mov.b64 {%0, %1}, %2;" : "=f"(f2), "=f"(f3) : "l"(acc[2 * m + 1]));
        ((float4*)hrow)[m] = make_float4(f0, f1, f2, f3);
        float4 bb = __ldg(&brow[m]);
        float4 ov;
        ov.x = fmaf(f0, sl, bb.x);
        ov.y = fmaf(f1, sl, bb.y);
        ov.z = fmaf(f2, sl, bb.z);
        ov.w = fmaf(f3, sl, bb.w);
        ((float4*)orow)[m] = ov;
    }
}

// ---------------------------------------------------------------------------
// 4) Edge scatter: out[dst] += h[src] * (dinv[src]*dinv[dst])
//    16 threads per edge, one float4 per thread, vector red.
//    (Measured at 65 us — L2 RMW traffic floor for this formulation.)
// ---------------------------------------------------------------------------
__global__ __launch_bounds__(256)
void scatter_kernel(const int* __restrict__ ei,
                    float* __restrict__ out, int E) {
    long long gid = (long long)blockIdx.x * blockDim.x + threadIdx.x;
    int e = (int)(gid >> 4);
    int l = (int)(gid & 15);
    if (e >= E) return;

    int s = __ldg(&ei[e]);        // src
    int d = __ldg(&ei[E + e]);    // dst
    float norm = g_dinv[s] * g_dinv[d];

    float4 v = ((const float4*)g_h)[(size_t)s * 16 + l];
    v.x *= norm; v.y *= norm; v.z *= norm; v.w *= norm;

    float* o = out + ((size_t)d * D + l * 4);
    asm volatile("red.global.add.v4.f32 [%0], {%1, %2, %3, %4};"
                 :: "l"(o), "f"(v.x), "f"(v.y), "f"(v.z), "f"(v.w)
                 : "memory");
}

// ---------------------------------------------------------------------------
extern "C" void kernel_launch(void* const* d_in, const int* in_sizes, int n_in,
                              void* d_out, int out_size) {
    const float* x  = (const float*)d_in[0];
    const int*   ei = (const int*)d_in[1];
    const float* W  = (const float*)d_in[2];
    const float* b  = (const float*)d_in[3];
    float*       out = (float*)d_out;

    int N = in_sizes[0] / D;   // 100000
    int E = in_sizes[1] / 2;   // 1000000

    int N4 = N / 4;            // N divisible by 4
    deg_init_kernel<<<(N4 + 255) / 256, 256>>>(N4);
    deg_acc_kernel<<<(E + 255) / 256, 256>>>(ei, E);
    gemm_kernel<<<(N + 63) / 64, 256>>>(x, W, b, out, N);

    long long total = (long long)E * 16;
    int nb_s = (int)((total + 255) / 256);
    scatter_kernel<<<nb_s, 256>>>(ei, out, E);
}

// round 8
// speedup vs baseline: 1.3598x; 1.3598x over previous
#include <cuda_runtime.h>

#define MAX_N 100000
#define D 64

// Scratch (device globals: sanctioned alternative to cudaMalloc)
__device__ float g_h[MAX_N * D];     // h = x @ W^T
__device__ float g_deg[MAX_N];
__device__ float g_dinv[MAX_N];
__device__ float g_Wt[D * D];        // W transposed: g_Wt[k*64+o] = W[o][k]

// ---------------------------------------------------------------------------
// 1) degree init: every node gets a self-loop -> deg starts at 1
// ---------------------------------------------------------------------------
__global__ void deg_init_kernel(int N4) {
    int i = blockIdx.x * blockDim.x + threadIdx.x;
    if (i < N4) ((float4*)g_deg)[i] = make_float4(1.f, 1.f, 1.f, 1.f);
}

// 2) accumulate in-degree over edge dst (edge_index is int32)
__global__ void deg_acc_kernel(const int* __restrict__ ei, int E) {
    int e = blockIdx.x * blockDim.x + threadIdx.x;
    if (e < E) atomicAdd(&g_deg[ei[E + e]], 1.0f);
}

// 3) transpose W once into gmem so gemm's smem fill is coalesced/conflict-free
__global__ void wt_kernel(const float* __restrict__ W) {
    int i = blockIdx.x * 256 + threadIdx.x;
    if (i < D * D) {
        int o = i >> 6, k = i & 63;
        g_Wt[k * D + o] = W[i];     // coalesced read, strided write (tiny)
    }
}

// ---------------------------------------------------------------------------
// 4) GEMM: h[n][o] = sum_k x[n][k] * W[o][k]
//    - x staged through smem with COALESCED gmem loads (read exactly once),
//      XOR-swizzled (float4 granularity) for conflict-free row reads.
//    - W smem fill from g_Wt: coalesced load, consecutive store (no conflict).
//    - Thread = (2 nodes, warp-uniform output quarter q): W LDS are broadcast
//      and amortized over 2 nodes; 16 f32x2 accumulators.
//    Epilogue: dinv, h, and out = h*dinv^2 + b (self-loop + bias; fully
//    initializes the poisoned output buffer).
// ---------------------------------------------------------------------------
__global__ __launch_bounds__(256)
void gemm_kernel(const float* __restrict__ x,
                 const float* __restrict__ bias,
                 float* __restrict__ out, int N) {
    __shared__ float Ws[D * D];        // Ws[k*64+o], natural layout
    __shared__ float Xs[128 * D];      // 128-node tile, XOR-swizzled float4s

    int tid = threadIdx.x;

    // W fill: both sides coalesced / conflict-free
    for (int t = tid; t < D * D; t += 256) Ws[t] = g_Wt[t];

    // x tile fill: consecutive lanes -> consecutive float4 (coalesced, 4 lines/LDG)
    int base = blockIdx.x * 128;
    int rows = N - base; if (rows > 128) rows = 128;
    const float4* xg = (const float4*)(x + (size_t)base * D);
    for (int t = tid; t < rows * 16; t += 256) {
        int r = t >> 4, j = t & 15;
        ((float4*)Xs)[r * 16 + (j ^ (r & 15))] = xg[t];
    }
    __syncthreads();

    int w    = tid >> 5;
    int lane = tid & 31;
    int q    = w & 3;                       // output quarter (warp-uniform)
    int rloc = (w >> 2) * 32 + lane;        // local row 0..63; 2nd node = +64
    int n0 = base + rloc;
    int n1 = n0 + 64;

    unsigned long long a0[8], a1[8];
#pragma unroll
    for (int m = 0; m < 8; m++) { a0[m] = 0ULL; a1[m] = 0ULL; }

    int sw = rloc & 15;
    const float4* xs0 = (const float4*)Xs + rloc * 16;
    const float4* xs1 = (const float4*)Xs + (rloc + 64) * 16;

#pragma unroll 1
    for (int i4 = 0; i4 < 16; i4++) {
        int jg = i4 ^ sw;
        float4 xa = xs0[jg];                // conflict-free (swizzled)
        float4 xb = xs1[jg];
        float fa[4] = {xa.x, xa.y, xa.z, xa.w};
        float fb[4] = {xb.x, xb.y, xb.z, xb.w};
#pragma unroll
        for (int kk = 0; kk < 4; kk++) {
            int k = i4 * 4 + kk;
            unsigned long long xx0, xx1;
            asm("mov.b64 %0, {%1, %1};" : "=l"(xx0) : "f"(fa[kk]));
            asm("mov.b64 %0, {%1, %1};" : "=l"(xx1) : "f"(fb[kk]));
            const ulonglong2* wp = (const ulonglong2*)(Ws + k * D + q * 16);
            ulonglong2 w0 = wp[0], w1 = wp[1], w2 = wp[2], w3 = wp[3];  // broadcast
            asm("fma.rn.f32x2 %0, %1, %2, %0;" : "+l"(a0[0]) : "l"(xx0), "l"(w0.x));
            asm("fma.rn.f32x2 %0, %1, %2, %0;" : "+l"(a0[1]) : "l"(xx0), "l"(w0.y));
            asm("fma.rn.f32x2 %0, %1, %2, %0;" : "+l"(a0[2]) : "l"(xx0), "l"(w1.x));
            asm("fma.rn.f32x2 %0, %1, %2, %0;" : "+l"(a0[3]) : "l"(xx0), "l"(w1.y));
            asm("fma.rn.f32x2 %0, %1, %2, %0;" : "+l"(a0[4]) : "l"(xx0), "l"(w2.x));
            asm("fma.rn.f32x2 %0, %1, %2, %0;" : "+l"(a0[5]) : "l"(xx0), "l"(w2.y));
            asm("fma.rn.f32x2 %0, %1, %2, %0;" : "+l"(a0[6]) : "l"(xx0), "l"(w3.x));
            asm("fma.rn.f32x2 %0, %1, %2, %0;" : "+l"(a0[7]) : "l"(xx0), "l"(w3.y));
            asm("fma.rn.f32x2 %0, %1, %2, %0;" : "+l"(a1[0]) : "l"(xx1), "l"(w0.x));
            asm("fma.rn.f32x2 %0, %1, %2, %0;" : "+l"(a1[1]) : "l"(xx1), "l"(w0.y));
            asm("fma.rn.f32x2 %0, %1, %2, %0;" : "+l"(a1[2]) : "l"(xx1), "l"(w1.x));
            asm("fma.rn.f32x2 %0, %1, %2, %0;" : "+l"(a1[3]) : "l"(xx1), "l"(w1.y));
            asm("fma.rn.f32x2 %0, %1, %2, %0;" : "+l"(a1[4]) : "l"(xx1), "l"(w2.x));
            asm("fma.rn.f32x2 %0, %1, %2, %0;" : "+l"(a1[5]) : "l"(xx1), "l"(w2.y));
            asm("fma.rn.f32x2 %0, %1, %2, %0;" : "+l"(a1[6]) : "l"(xx1), "l"(w3.x));
            asm("fma.rn.f32x2 %0, %1, %2, %0;" : "+l"(a1[7]) : "l"(xx1), "l"(w3.y));
        }
    }

    const float4* brow = (const float4*)(bias + q * 16);   // warp-uniform
    float4 bb0 = __ldg(&brow[0]), bb1 = __ldg(&brow[1]);
    float4 bb2 = __ldg(&brow[2]), bb3 = __ldg(&brow[3]);
    float4 bbs[4] = {bb0, bb1, bb2, bb3};

#pragma unroll
    for (int jn = 0; jn < 2; jn++) {
        int n = (jn == 0) ? n0 : n1;
        if (n >= N) continue;
        unsigned long long* acc = (jn == 0) ? a0 : a1;
        float dv = rsqrtf(g_deg[n]);
        if (q == 0) g_dinv[n] = dv;
        float sl = dv * dv;
        float* hrow = g_h + (size_t)n * D + q * 16;
        float* orow = out + (size_t)n * D + q * 16;
#pragma unroll
        for (int m = 0; m < 4; m++) {
            float f0, f1, f2, f3;
            asm("mov.b64 {%0, %1}, %2;" : "=f"(f0), "=f"(f1) : "l"(acc[2 * m]));
            asm("mov.b64 {%0, %1}, %2;" : "=f"(f2), "=f"(f3) : "l"(acc[2 * m + 1]));
            ((float4*)hrow)[m] = make_float4(f0, f1, f2, f3);
            float4 bb = bbs[m];
            float4 ov;
            ov.x = fmaf(f0, sl, bb.x);
            ov.y = fmaf(f1, sl, bb.y);
            ov.z = fmaf(f2, sl, bb.z);
            ov.w = fmaf(f3, sl, bb.w);
            ((float4*)orow)[m] = ov;
        }
    }
}

// ---------------------------------------------------------------------------
// 5) Edge scatter: out[dst] += h[src] * (dinv[src]*dinv[dst])
//    16 threads per edge, one float4 per thread, vector red.
//    (Measured 65 us — L2 RMW floor for this formulation.)
// ---------------------------------------------------------------------------
__global__ __launch_bounds__(256)
void scatter_kernel(const int* __restrict__ ei,
                    float* __restrict__ out, int E) {
    long long gid = (long long)blockIdx.x * blockDim.x + threadIdx.x;
    int e = (int)(gid >> 4);
    int l = (int)(gid & 15);
    if (e >= E) return;

    int s = __ldg(&ei[e]);        // src
    int d = __ldg(&ei[E + e]);    // dst
    float norm = g_dinv[s] * g_dinv[d];

    float4 v = ((const float4*)g_h)[(size_t)s * 16 + l];
    v.x *= norm; v.y *= norm; v.z *= norm; v.w *= norm;

    float* o = out + ((size_t)d * D + l * 4);
    asm volatile("red.global.add.v4.f32 [%0], {%1, %2, %3, %4};"
                 :: "l"(o), "f"(v.x), "f"(v.y), "f"(v.z), "f"(v.w)
                 : "memory");
}

// ---------------------------------------------------------------------------
extern "C" void kernel_launch(void* const* d_in, const int* in_sizes, int n_in,
                              void* d_out, int out_size) {
    const float* x  = (const float*)d_in[0];
    const int*   ei = (const int*)d_in[1];
    const float* W  = (const float*)d_in[2];
    const float* b  = (const float*)d_in[3];
    float*       out = (float*)d_out;

    int N = in_sizes[0] / D;   // 100000
    int E = in_sizes[1] / 2;   // 1000000

    int N4 = N / 4;            // N divisible by 4
    deg_init_kernel<<<(N4 + 255) / 256, 256>>>(N4);
    deg_acc_kernel<<<(E + 255) / 256, 256>>>(ei, E);
    wt_kernel<<<16, 256>>>(W);
    gemm_kernel<<<(N + 127) / 128, 256>>>(x, b, out, N);

    long long total = (long long)E * 16;
    int nb_s = (int)((total + 255) / 256);
    scatter_kernel<<<nb_s, 256>>>(ei, out, E);
}